// round 2
// baseline (speedup 1.0000x reference)
#include <cuda_runtime.h>
#include <cstdint>

// -------------------------------------------------------------------------
// EuclideanGraphDecoder: 3x GCN layer (linear -> adj-aggregate -> relu) + proj
// B=8, N=2048, latent=64, hidden=128, out=64.  All fp32 (round-1 baseline).
//
// Pipeline (all through a generic tiled SGEMM):
//   msg0 = latent @ W0 + b0            gemm128<bias>
//   h1   = relu(adj @ msg0)            gemm128<relu>  (batched)
//   msg1 = h1 @ W1 + b1
//   h2   = relu(adj @ msg1)
//   msg2 = h2 @ W2 + b2
//   h3   = relu(adj @ msg2)
//   out  = (h3 @ Wout + bout) * mask   final_proj
// -------------------------------------------------------------------------

#define BATCH   8
#define NNODES  2048
#define HID     128
#define ROWS_T  (BATCH * NNODES)     // 16384

// Scratch ping-pong buffers: [16384, 128] fp32 = 8 MB each (device globals,
// allocation-free per harness rules).
__device__ float g_buf0[ROWS_T * HID];
__device__ float g_buf1[ROWS_T * HID];

// -------------------------------------------------------------------------
// Generic tiled SGEMM:  C[M,128] = op(A[M,K] @ B[K,128])
//   TM=128, TN=128, TK=8, 256 threads, 8x8 microtile per thread.
//   blockIdx.x = M tile, blockIdx.y = batch (strided A/B/C).
//   BIAS: add bias[col];  RELU: clamp at 0.
// Requires M % 128 == 0, K % 8 == 0 (holds for all call sites).
// -------------------------------------------------------------------------
template<bool RELU, bool BIAS>
__global__ __launch_bounds__(256)
void gemm128(const float* __restrict__ A, const float* __restrict__ B,
             const float* __restrict__ bias, float* __restrict__ C,
             int K, size_t sA, size_t sB, size_t sC)
{
    const int batch = blockIdx.y;
    const int m0    = blockIdx.x * 128;

    const float* Ap = A + (size_t)batch * sA + (size_t)m0 * K;
    const float* Bp = B + (size_t)batch * sB;
    float*       Cp = C + (size_t)batch * sC + (size_t)m0 * 128;

    __shared__ float As[8][128];   // transposed A tile: As[k][m]
    __shared__ float Bs[8][128];   // Bs[k][n]

    const int tid = threadIdx.x;
    const int tx  = tid & 15;      // 0..15  (col group)
    const int ty  = tid >> 4;      // 0..15  (row group)

    // global-load assignments
    const int a_row = tid >> 1;           // 0..127
    const int a_k   = (tid & 1) * 4;      // 0 or 4
    const int b_row = tid >> 5;           // 0..7
    const int b_col = (tid & 31) * 4;     // 0..124

    float acc[8][8];
#pragma unroll
    for (int i = 0; i < 8; i++)
#pragma unroll
        for (int j = 0; j < 8; j++) acc[i][j] = 0.0f;

    const int ktiles = K >> 3;

    // prologue load (tile 0)
    float4 ra = *(const float4*)(Ap + (size_t)a_row * K + a_k);
    float4 rb = *(const float4*)(Bp + (size_t)b_row * 128 + b_col);

    for (int kt = 0; kt < ktiles; kt++) {
        // stage current tile into smem
        As[a_k + 0][a_row] = ra.x;
        As[a_k + 1][a_row] = ra.y;
        As[a_k + 2][a_row] = ra.z;
        As[a_k + 3][a_row] = ra.w;
        *(float4*)&Bs[b_row][b_col] = rb;
        __syncthreads();

        // prefetch next tile (LDG overlaps compute below)
        if (kt + 1 < ktiles) {
            const int kn = (kt + 1) * 8;
            ra = *(const float4*)(Ap + (size_t)a_row * K + kn + a_k);
            rb = *(const float4*)(Bp + (size_t)(kn + b_row) * 128 + b_col);
        }

#pragma unroll
        for (int kk = 0; kk < 8; kk++) {
            float af[8], bf[8];
            *(float4*)&af[0] = *(const float4*)&As[kk][ty * 4];
            *(float4*)&af[4] = *(const float4*)&As[kk][64 + ty * 4];
            *(float4*)&bf[0] = *(const float4*)&Bs[kk][tx * 4];
            *(float4*)&bf[4] = *(const float4*)&Bs[kk][64 + tx * 4];
#pragma unroll
            for (int i = 0; i < 8; i++)
#pragma unroll
                for (int j = 0; j < 8; j++)
                    acc[i][j] += af[i] * bf[j];
        }
        __syncthreads();
    }

    // epilogue
    float bfrag[8];
    if (BIAS) {
#pragma unroll
        for (int q = 0; q < 4; q++) {
            bfrag[q]     = bias[tx * 4 + q];
            bfrag[4 + q] = bias[64 + tx * 4 + q];
        }
    }

#pragma unroll
    for (int i = 0; i < 8; i++) {
        const int row = (i < 4) ? (ty * 4 + i) : (64 + ty * 4 + (i - 4));
#pragma unroll
        for (int jg = 0; jg < 2; jg++) {
            float4 v;
            float* vp = &v.x;
#pragma unroll
            for (int q = 0; q < 4; q++) {
                float x = acc[i][jg * 4 + q];
                if (BIAS) x += bfrag[jg * 4 + q];
                if (RELU) x = fmaxf(x, 0.0f);
                vp[q] = x;
            }
            *(float4*)(Cp + (size_t)row * 128 + jg * 64 + tx * 4) = v;
        }
    }
}

// -------------------------------------------------------------------------
// Output projection: out[r, 0:64] = (h[r, 0:128] @ Wout[128,64] + bout) * mask[r]
// Block = 256 threads, processes 16 rows; Wout cached in smem.
// -------------------------------------------------------------------------
__global__ __launch_bounds__(256)
void final_proj_kernel(const float* __restrict__ h, const float* __restrict__ W,
                       const float* __restrict__ bias, const float* __restrict__ mask,
                       float* __restrict__ out)
{
    __shared__ float Ws[128][64];   // 32 KB
    __shared__ float xs[16][128];   // 8 KB
    __shared__ float bs[64];

    const int tid = threadIdx.x;

    // cooperative load W (8192 floats = 2048 float4)
    for (int i = tid; i < 2048; i += 256)
        ((float4*)&Ws[0][0])[i] = ((const float4*)W)[i];
    if (tid < 64) bs[tid] = bias[tid];

    const int row0 = blockIdx.x * 16;
    // cooperative load 16 h rows (2048 floats = 512 float4)
    for (int i = tid; i < 512; i += 256)
        ((float4*)&xs[0][0])[i] = *(const float4*)(h + (size_t)row0 * 128 + i * 4);
    __syncthreads();

    const int rl = tid >> 4;        // 0..15 local row
    const int c4 = (tid & 15) * 4;  // 0..60 col base

    float acc[4];
#pragma unroll
    for (int q = 0; q < 4; q++) acc[q] = bs[c4 + q];

#pragma unroll 8
    for (int d = 0; d < 128; d++) {
        const float x = xs[rl][d];
        const float4 w = *(const float4*)&Ws[d][c4];
        acc[0] += x * w.x;
        acc[1] += x * w.y;
        acc[2] += x * w.z;
        acc[3] += x * w.w;
    }

    const float m = mask[row0 + rl];
    float4 v = {acc[0] * m, acc[1] * m, acc[2] * m, acc[3] * m};
    *(float4*)(out + (size_t)(row0 + rl) * 64 + c4) = v;
}

// -------------------------------------------------------------------------
// Launcher
// -------------------------------------------------------------------------
extern "C" void kernel_launch(void* const* d_in, const int* in_sizes, int n_in,
                              void* d_out, int out_size)
{
    const float* latent = (const float*)d_in[0];   // [8,2048,64]
    const float* adj    = (const float*)d_in[1];   // [8,2048,2048]
    const float* mask   = (const float*)d_in[2];   // [8,2048,1]
    const float* W0     = (const float*)d_in[3];   // [64,128]
    const float* b0     = (const float*)d_in[4];
    const float* W1     = (const float*)d_in[5];   // [128,128]
    const float* b1     = (const float*)d_in[6];
    const float* W2     = (const float*)d_in[7];   // [128,128]
    const float* b2     = (const float*)d_in[8];
    const float* Wout   = (const float*)d_in[9];   // [128,64]
    const float* bout   = (const float*)d_in[10];
    float*       out    = (float*)d_out;           // [8,2048,64]

    float *buf0 = nullptr, *buf1 = nullptr;
    cudaGetSymbolAddress((void**)&buf0, g_buf0);
    cudaGetSymbolAddress((void**)&buf1, g_buf1);

    const dim3 gridLin(ROWS_T / 128, 1);   // 128 blocks
    const dim3 gridAgg(NNODES / 128, BATCH); // 16 x 8 = 128 blocks
    const size_t sAdj = (size_t)NNODES * NNODES;
    const size_t sH   = (size_t)NNODES * HID;

    // layer 0: msg = latent @ W0 + b0   (K=64)
    gemm128<false, true><<<gridLin, 256>>>(latent, W0, b0, buf0, 64, 0, 0, 0);
    // h1 = relu(adj @ msg)              (batched, K=2048)
    gemm128<true, false><<<gridAgg, 256>>>(adj, buf0, nullptr, buf1, NNODES, sAdj, sH, sH);

    // layer 1
    gemm128<false, true><<<gridLin, 256>>>(buf1, W1, b1, buf0, 128, 0, 0, 0);
    gemm128<true, false><<<gridAgg, 256>>>(adj, buf0, nullptr, buf1, NNODES, sAdj, sH, sH);

    // layer 2
    gemm128<false, true><<<gridLin, 256>>>(buf1, W2, b2, buf0, 128, 0, 0, 0);
    gemm128<true, false><<<gridAgg, 256>>>(adj, buf0, nullptr, buf1, NNODES, sAdj, sH, sH);

    // output projection + mask
    final_proj_kernel<<<ROWS_T / 16, 256>>>(buf1, Wout, bout, mask, out);
}

// round 4
// speedup vs baseline: 1.9715x; 1.9715x over previous
#include <cuda_runtime.h>
#include <cstdint>

// =========================================================================
// EuclideanGraphDecoder on GB300 (sm_103a, compiled as compute_103 baseline)
// B=8, N=2048, latent=64, hidden=128, out=64, NORM=1.
//
//   msg = h @ W + b                  (fp32 FFMA gemm, small K)
//   h'  = relu(adj @ msg)            (mma.sync tf32 tensor cores, RNA-rounded)
//   x3 layers, then out = (h @ Wout + bout) * mask
//
// tcgen05 PTX is rejected by this toolchain (targets compute_103, not 103a),
// so the aggregation GEMM uses mma.sync.m16n8k8.tf32 (sm_80+ baseline PTX).
// =========================================================================

#define BATCH   8
#define NNODES  2048
#define HID     128
#define ROWS_T  (BATCH * NNODES)     // 16384

__device__ float g_buf0[ROWS_T * HID];   // msg (node-major [n][f])
__device__ float g_buf1[ROWS_T * HID];   // h   (node-major [n][f])

// ---------------------------------------------------------------- helpers
__device__ __forceinline__ uint32_t cvt_rna_tf32(float x) {
    uint32_t y;
    asm("cvt.rna.tf32.f32 %0, %1;" : "=r"(y) : "f"(x));
    return y;
}

__device__ __forceinline__ void mma_tf32(float& c0, float& c1, float& c2, float& c3,
                                         uint32_t a0, uint32_t a1, uint32_t a2, uint32_t a3,
                                         uint32_t b0, uint32_t b1) {
    asm volatile(
        "mma.sync.aligned.m16n8k8.row.col.f32.tf32.tf32.f32 "
        "{%0,%1,%2,%3}, {%4,%5,%6,%7}, {%8,%9}, {%0,%1,%2,%3};"
        : "+f"(c0), "+f"(c1), "+f"(c2), "+f"(c3)
        : "r"(a0), "r"(a1), "r"(a2), "r"(a3), "r"(b0), "r"(b1));
}

// =========================================================================
// Aggregation GEMM (tensor cores):
//   h[b, m0:m0+128, :] = relu( adj[b, m0:m0+128, :] @ msg[b, :, :] )
// CTA tile 128x128, K=2048 in BK=32 chunks, double-buffered SMEM.
// 8 warps in a 4(M) x 2(N) grid; warp tile 32x64 = 2x8 m16n8k8 tiles.
// SMEM: As[m][36] (pad 4), Bs[k][136] (pad 8) -> conflict-free lds/sts.
// =========================================================================
#define BK     32
#define KITERS (NNODES / BK)     // 64
#define ASTRIDE 36               // 32 + 4 pad (floats)
#define BSTRIDE 136              // 128 + 8 pad (floats)
#define ASZ (128 * ASTRIDE)      // floats per A stage
#define BSZ (BK * BSTRIDE)       // floats per B stage
#define AGG_SMEM ((2 * ASZ + 2 * BSZ) * 4)   // 71680 bytes

__global__ __launch_bounds__(256, 1)
void agg_mma_kernel(const float* __restrict__ adj, const float* __restrict__ msg,
                    float* __restrict__ hout)
{
    extern __shared__ float sm[];
    float* As[2] = { sm,             sm + ASZ };
    float* Bs[2] = { sm + 2 * ASZ,   sm + 2 * ASZ + BSZ };

    const int tid   = threadIdx.x;
    const int lane  = tid & 31;
    const int wid   = tid >> 5;
    const int g     = lane >> 2;       // group id 0..7
    const int tig   = lane & 3;        // thread-in-group 0..3
    const int warpM = wid & 3;         // 0..3  -> mbase = warpM*32
    const int warpN = wid >> 2;        // 0..1  -> nbase = warpN*64
    const int mbase = warpM * 32;
    const int nbase = warpN * 64;

    const int batch = blockIdx.y;
    const int m0    = blockIdx.x * 128;

    const float* Ap = adj + (size_t)batch * NNODES * NNODES + (size_t)m0 * NNODES;
    const float* Bp = msg + (size_t)batch * NNODES * HID;

    // staging assignment
    const int tm = tid >> 3;   // 0..31
    const int tc = tid & 7;    // 0..7

    float acc[2][8][4];
#pragma unroll
    for (int t = 0; t < 2; t++)
#pragma unroll
        for (int u = 0; u < 8; u++)
#pragma unroll
            for (int q = 0; q < 4; q++) acc[t][u][q] = 0.0f;

    // prologue global loads (chunk 0)
    float4 va[4], vb[4];
#pragma unroll
    for (int r = 0; r < 4; r++) {
        va[r] = *(const float4*)(Ap + (size_t)(tm + 32 * r) * NNODES + 4 * tc);
        vb[r] = *(const float4*)(Bp + (size_t)tm * HID + 4 * (tc + 8 * r));
    }

    for (int it = 0; it < KITERS; it++) {
        float* as = As[it & 1];
        float* bs = Bs[it & 1];
        const uint32_t* asu = (const uint32_t*)as;
        const uint32_t* bsu = (const uint32_t*)bs;

        // ---- stage current chunk into smem (RNA-round to tf32) ----
#pragma unroll
        for (int r = 0; r < 4; r++) {
            uint4 a4;
            a4.x = cvt_rna_tf32(va[r].x); a4.y = cvt_rna_tf32(va[r].y);
            a4.z = cvt_rna_tf32(va[r].z); a4.w = cvt_rna_tf32(va[r].w);
            *(uint4*)(as + (tm + 32 * r) * ASTRIDE + 4 * tc) = a4;

            uint4 b4;
            b4.x = cvt_rna_tf32(vb[r].x); b4.y = cvt_rna_tf32(vb[r].y);
            b4.z = cvt_rna_tf32(vb[r].z); b4.w = cvt_rna_tf32(vb[r].w);
            *(uint4*)(bs + tm * BSTRIDE + 4 * (tc + 8 * r)) = b4;
        }
        __syncthreads();

        // ---- prefetch next chunk into registers ----
        if (it + 1 < KITERS) {
            const int k0 = (it + 1) * BK;
#pragma unroll
            for (int r = 0; r < 4; r++) {
                va[r] = *(const float4*)(Ap + (size_t)(tm + 32 * r) * NNODES + k0 + 4 * tc);
                vb[r] = *(const float4*)(Bp + (size_t)(k0 + tm) * HID + 4 * (tc + 8 * r));
            }
        }

        // ---- 4 k-steps of m16n8k8 ----
#pragma unroll
        for (int ks = 0; ks < 4; ks++) {
            const int k = ks * 8;
            uint32_t af[2][4];
#pragma unroll
            for (int t = 0; t < 2; t++) {
                const int m = mbase + t * 16 + g;
                af[t][0] = asu[m * ASTRIDE + k + tig];
                af[t][1] = asu[(m + 8) * ASTRIDE + k + tig];
                af[t][2] = asu[m * ASTRIDE + k + tig + 4];
                af[t][3] = asu[(m + 8) * ASTRIDE + k + tig + 4];
            }
#pragma unroll
            for (int u = 0; u < 8; u++) {
                const int n = nbase + u * 8 + g;
                const uint32_t b0 = bsu[(k + tig) * BSTRIDE + n];
                const uint32_t b1 = bsu[(k + tig + 4) * BSTRIDE + n];
#pragma unroll
                for (int t = 0; t < 2; t++)
                    mma_tf32(acc[t][u][0], acc[t][u][1], acc[t][u][2], acc[t][u][3],
                             af[t][0], af[t][1], af[t][2], af[t][3], b0, b1);
            }
        }
        __syncthreads();
    }

    // ---- epilogue: relu + store ----
    float* Cp = hout + (size_t)batch * NNODES * HID + (size_t)m0 * HID;
#pragma unroll
    for (int t = 0; t < 2; t++) {
        const int r0 = mbase + t * 16 + g;
#pragma unroll
        for (int u = 0; u < 8; u++) {
            const int c = nbase + u * 8 + 2 * tig;
            float2 v0 = { fmaxf(acc[t][u][0], 0.0f), fmaxf(acc[t][u][1], 0.0f) };
            float2 v1 = { fmaxf(acc[t][u][2], 0.0f), fmaxf(acc[t][u][3], 0.0f) };
            *(float2*)(Cp + (size_t)r0 * HID + c)       = v0;
            *(float2*)(Cp + (size_t)(r0 + 8) * HID + c) = v1;
        }
    }
}

// =========================================================================
// Linear layer (fp32 FFMA): C[M,128] = A[M,K] @ W[K,128] + b   (node-major)
// =========================================================================
template<bool RELU, bool BIAS>
__global__ __launch_bounds__(256)
void gemm128(const float* __restrict__ A, const float* __restrict__ B,
             const float* __restrict__ bias, float* __restrict__ C,
             int K, size_t sA, size_t sB, size_t sC)
{
    const int batch = blockIdx.y;
    const int m0    = blockIdx.x * 128;

    const float* Ap = A + (size_t)batch * sA + (size_t)m0 * K;
    const float* Bp = B + (size_t)batch * sB;
    float*       Cp = C + (size_t)batch * sC + (size_t)m0 * 128;

    __shared__ float As[8][128];
    __shared__ float Bs[8][128];

    const int tid = threadIdx.x;
    const int tx  = tid & 15;
    const int ty  = tid >> 4;

    const int a_row = tid >> 1;
    const int a_k   = (tid & 1) * 4;
    const int b_row = tid >> 5;
    const int b_col = (tid & 31) * 4;

    float acc[8][8];
#pragma unroll
    for (int i = 0; i < 8; i++)
#pragma unroll
        for (int j = 0; j < 8; j++) acc[i][j] = 0.0f;

    const int ktiles = K >> 3;
    float4 ra = *(const float4*)(Ap + (size_t)a_row * K + a_k);
    float4 rb = *(const float4*)(Bp + (size_t)b_row * 128 + b_col);

    for (int kt = 0; kt < ktiles; kt++) {
        As[a_k + 0][a_row] = ra.x;
        As[a_k + 1][a_row] = ra.y;
        As[a_k + 2][a_row] = ra.z;
        As[a_k + 3][a_row] = ra.w;
        *(float4*)&Bs[b_row][b_col] = rb;
        __syncthreads();

        if (kt + 1 < ktiles) {
            const int kn = (kt + 1) * 8;
            ra = *(const float4*)(Ap + (size_t)a_row * K + kn + a_k);
            rb = *(const float4*)(Bp + (size_t)(kn + b_row) * 128 + b_col);
        }

#pragma unroll
        for (int kk = 0; kk < 8; kk++) {
            float af[8], bf[8];
            *(float4*)&af[0] = *(const float4*)&As[kk][ty * 4];
            *(float4*)&af[4] = *(const float4*)&As[kk][64 + ty * 4];
            *(float4*)&bf[0] = *(const float4*)&Bs[kk][tx * 4];
            *(float4*)&bf[4] = *(const float4*)&Bs[kk][64 + tx * 4];
#pragma unroll
            for (int i = 0; i < 8; i++)
#pragma unroll
                for (int j = 0; j < 8; j++)
                    acc[i][j] += af[i] * bf[j];
        }
        __syncthreads();
    }

    float bfrag[8];
    if (BIAS) {
#pragma unroll
        for (int q = 0; q < 4; q++) {
            bfrag[q]     = bias[tx * 4 + q];
            bfrag[4 + q] = bias[64 + tx * 4 + q];
        }
    }

#pragma unroll
    for (int i = 0; i < 8; i++) {
        const int row = (i < 4) ? (ty * 4 + i) : (64 + ty * 4 + (i - 4));
#pragma unroll
        for (int jg = 0; jg < 2; jg++) {
            float4 v;
            float* vp = &v.x;
#pragma unroll
            for (int q = 0; q < 4; q++) {
                float x = acc[i][jg * 4 + q];
                if (BIAS) x += bfrag[jg * 4 + q];
                if (RELU) x = fmaxf(x, 0.0f);
                vp[q] = x;
            }
            *(float4*)(Cp + (size_t)row * 128 + jg * 64 + tx * 4) = v;
        }
    }
}

// =========================================================================
// Output projection: out = (h @ Wout + bout) * mask
// =========================================================================
__global__ __launch_bounds__(256)
void final_proj_kernel(const float* __restrict__ h, const float* __restrict__ W,
                       const float* __restrict__ bias, const float* __restrict__ mask,
                       float* __restrict__ out)
{
    __shared__ float Ws[128][64];
    __shared__ float xs[16][128];
    __shared__ float bs[64];

    const int tid = threadIdx.x;
    for (int i = tid; i < 2048; i += 256)
        ((float4*)&Ws[0][0])[i] = ((const float4*)W)[i];
    if (tid < 64) bs[tid] = bias[tid];

    const int row0 = blockIdx.x * 16;
    for (int i = tid; i < 512; i += 256)
        ((float4*)&xs[0][0])[i] = *(const float4*)(h + (size_t)row0 * 128 + i * 4);
    __syncthreads();

    const int rl = tid >> 4;
    const int c4 = (tid & 15) * 4;

    float acc[4];
#pragma unroll
    for (int q = 0; q < 4; q++) acc[q] = bs[c4 + q];

#pragma unroll 8
    for (int d = 0; d < 128; d++) {
        const float x = xs[rl][d];
        const float4 w = *(const float4*)&Ws[d][c4];
        acc[0] += x * w.x;
        acc[1] += x * w.y;
        acc[2] += x * w.z;
        acc[3] += x * w.w;
    }

    const float m = mask[row0 + rl];
    float4 v = {acc[0] * m, acc[1] * m, acc[2] * m, acc[3] * m};
    *(float4*)(out + (size_t)(row0 + rl) * 64 + c4) = v;
}

// =========================================================================
// Launcher
// =========================================================================
extern "C" void kernel_launch(void* const* d_in, const int* in_sizes, int n_in,
                              void* d_out, int out_size)
{
    const float* latent = (const float*)d_in[0];
    const float* adj    = (const float*)d_in[1];
    const float* mask   = (const float*)d_in[2];
    const float* W0     = (const float*)d_in[3];
    const float* b0     = (const float*)d_in[4];
    const float* W1     = (const float*)d_in[5];
    const float* b1     = (const float*)d_in[6];
    const float* W2     = (const float*)d_in[7];
    const float* b2     = (const float*)d_in[8];
    const float* Wout   = (const float*)d_in[9];
    const float* bout   = (const float*)d_in[10];
    float*       out    = (float*)d_out;

    float *buf0 = nullptr, *buf1 = nullptr;
    cudaGetSymbolAddress((void**)&buf0, g_buf0);
    cudaGetSymbolAddress((void**)&buf1, g_buf1);

    cudaFuncSetAttribute(agg_mma_kernel,
                         cudaFuncAttributeMaxDynamicSharedMemorySize, AGG_SMEM);

    const dim3 gridLin(ROWS_T / 128, 1);
    const dim3 gridAgg(NNODES / 128, BATCH);   // 16 x 8 = 128 CTAs

    // layer 0
    gemm128<false, true><<<gridLin, 256>>>(latent, W0, b0, buf0, 64, 0, 0, 0);
    agg_mma_kernel<<<gridAgg, 256, AGG_SMEM>>>(adj, buf0, buf1);

    // layer 1
    gemm128<false, true><<<gridLin, 256>>>(buf1, W1, b1, buf0, 128, 0, 0, 0);
    agg_mma_kernel<<<gridAgg, 256, AGG_SMEM>>>(adj, buf0, buf1);

    // layer 2
    gemm128<false, true><<<gridLin, 256>>>(buf1, W2, b2, buf0, 128, 0, 0, 0);
    agg_mma_kernel<<<gridAgg, 256, AGG_SMEM>>>(adj, buf0, buf1);

    // output projection + mask
    final_proj_kernel<<<ROWS_T / 16, 256>>>(buf1, Wout, bout, mask, out);
}

// round 6
// speedup vs baseline: 2.4010x; 1.2179x over previous
#include <cuda_runtime.h>
#include <cstdint>

// =========================================================================
// EuclideanGraphDecoder on GB300 (sm_103a via compute_103 baseline PTX)
// B=8, N=2048, latent=64, hidden=128, out=64, NORM=1.
//
// R5: adjacency pre-rounded to tf32 bits once; msg rounded in linear
// epilogue; agg GEMM = mma.sync.m16n8k8.tf32 with 4-stage cp.async pipeline.
// =========================================================================

#define BATCH   8
#define NNODES  2048
#define HID     128
#define ROWS_T  (BATCH * NNODES)     // 16384
#define ADJ_ELEMS ((size_t)BATCH * NNODES * NNODES)   // 33,554,432

__device__ float g_buf0[ROWS_T * HID];     // msg (node-major, tf32-rounded)
__device__ float g_buf1[ROWS_T * HID];     // h   (node-major, fp32)
__device__ float g_adj32[ADJ_ELEMS];       // adjacency, RNA-rounded tf32 bits

// ---------------------------------------------------------------- helpers
__device__ __forceinline__ uint32_t cvt_rna_tf32(float x) {
    uint32_t y;
    asm("cvt.rna.tf32.f32 %0, %1;" : "=r"(y) : "f"(x));
    return y;
}
__device__ __forceinline__ uint32_t smem_u32(const void* p) {
    uint32_t a;
    asm("{ .reg .u64 t; cvta.to.shared.u64 t, %1; cvt.u32.u64 %0, t; }" : "=r"(a) : "l"(p));
    return a;
}
__device__ __forceinline__ void cp_async16(uint32_t dst, const void* src) {
    asm volatile("cp.async.cg.shared.global [%0], [%1], 16;" :: "r"(dst), "l"(src));
}
#define CP_COMMIT() asm volatile("cp.async.commit_group;" ::: "memory")

__device__ __forceinline__ void mma_tf32(float& c0, float& c1, float& c2, float& c3,
                                         uint32_t a0, uint32_t a1, uint32_t a2, uint32_t a3,
                                         uint32_t b0, uint32_t b1) {
    asm volatile(
        "mma.sync.aligned.m16n8k8.row.col.f32.tf32.tf32.f32 "
        "{%0,%1,%2,%3}, {%4,%5,%6,%7}, {%8,%9}, {%0,%1,%2,%3};"
        : "+f"(c0), "+f"(c1), "+f"(c2), "+f"(c3)
        : "r"(a0), "r"(a1), "r"(a2), "r"(a3), "r"(b0), "r"(b1));
}

// =========================================================================
// Adjacency pre-round: g_adj32 = round_rna_tf32(adj)
// =========================================================================
__global__ __launch_bounds__(256)
void round_adj_kernel(const float* __restrict__ in, float* __restrict__ out)
{
    const size_t n4 = ADJ_ELEMS / 4;
    const size_t stride = (size_t)gridDim.x * 256;
    for (size_t i = (size_t)blockIdx.x * 256 + threadIdx.x; i < n4; i += stride) {
        float4 v = ((const float4*)in)[i];
        uint4 u;
        u.x = cvt_rna_tf32(v.x); u.y = cvt_rna_tf32(v.y);
        u.z = cvt_rna_tf32(v.z); u.w = cvt_rna_tf32(v.w);
        ((uint4*)out)[i] = u;
    }
}

// =========================================================================
// Aggregation GEMM (tensor cores, cp.async pipeline):
//   h[b, m0:m0+128, :] = relu( adjT32[b, m0:m0+128, :] @ msg[b, :, :] )
// CTA 128x128, K in BK=32 chunks, 4-stage cp.async double... quad buffering.
// 8 warps 4(M)x2(N), warp tile 32x64 = 2x8 m16n8k8.
// SMEM per stage: A 128x36 floats (pad 4), B 32x136 floats (pad 8).
// =========================================================================
#define BK      32
#define KITERS  (NNODES / BK)        // 64
#define STG     4
#define ASTRIDE 36
#define BSTRIDE 136
#define A_FLTS  (128 * ASTRIDE)      // 4608
#define B_FLTS  (BK * BSTRIDE)       // 4352
#define STG_FLTS (A_FLTS + B_FLTS)   // 8960
#define AGG_SMEM (STG * STG_FLTS * 4)   // 143360 bytes

__device__ __forceinline__ void stage_chunk(uint32_t smb, int s,
                                            const float* Ap, const float* Bp,
                                            int k0, int tid)
{
    const uint32_t sa = smb + (uint32_t)(s * STG_FLTS) * 4u;
    const uint32_t sb = sa + A_FLTS * 4u;
#pragma unroll
    for (int r = 0; r < 4; r++) {
        const int idx  = tid + 256 * r;
        const int arow = idx >> 3, aseg = idx & 7;
        cp_async16(sa + (uint32_t)(arow * ASTRIDE + aseg * 4) * 4u,
                   Ap + (size_t)arow * NNODES + k0 + aseg * 4);
        const int brow = idx >> 5, bseg = idx & 31;
        cp_async16(sb + (uint32_t)(brow * BSTRIDE + bseg * 4) * 4u,
                   Bp + (size_t)(k0 + brow) * HID + bseg * 4);
    }
    CP_COMMIT();
}

__global__ __launch_bounds__(256, 1)
void agg_mma_kernel(const float* __restrict__ adjT32, const float* __restrict__ msg,
                    float* __restrict__ hout)
{
    extern __shared__ float sm[];
    const uint32_t smb = smem_u32(sm);

    const int tid   = threadIdx.x;
    const int lane  = tid & 31;
    const int wid   = tid >> 5;
    const int g     = lane >> 2;       // 0..7
    const int tig   = lane & 3;        // 0..3
    const int mbase = (wid & 3) * 32;  // 4 warps along M
    const int nbase = (wid >> 2) * 64; // 2 warps along N

    const int batch = blockIdx.y;
    const int m0    = blockIdx.x * 128;

    const float* Ap = adjT32 + (size_t)batch * NNODES * NNODES + (size_t)m0 * NNODES;
    const float* Bp = msg    + (size_t)batch * NNODES * HID;

    float acc[2][8][4];
#pragma unroll
    for (int t = 0; t < 2; t++)
#pragma unroll
        for (int u = 0; u < 8; u++)
#pragma unroll
            for (int q = 0; q < 4; q++) acc[t][u][q] = 0.0f;

    // prologue: stage chunks 0..2
#pragma unroll
    for (int p = 0; p < STG - 1; p++)
        stage_chunk(smb, p, Ap, Bp, p * BK, tid);

    for (int it = 0; it < KITERS; it++) {
        // wait until chunk `it` has landed
        if (it < KITERS - 2)      asm volatile("cp.async.wait_group 2;" ::: "memory");
        else if (it < KITERS - 1) asm volatile("cp.async.wait_group 1;" ::: "memory");
        else                      asm volatile("cp.async.wait_group 0;" ::: "memory");
        __syncthreads();

        // refill the stage freed at the previous iteration
        if (it + STG - 1 < KITERS)
            stage_chunk(smb, (it + STG - 1) & (STG - 1), Ap, Bp, (it + STG - 1) * BK, tid);

        const uint32_t* asu = (const uint32_t*)(sm + (it & (STG - 1)) * STG_FLTS);
        const uint32_t* bsu = asu + A_FLTS;

#pragma unroll
        for (int ks = 0; ks < 4; ks++) {
            const int k = ks * 8;
            uint32_t af[2][4];
#pragma unroll
            for (int t = 0; t < 2; t++) {
                const int m = mbase + t * 16 + g;
                af[t][0] = asu[m * ASTRIDE + k + tig];
                af[t][1] = asu[(m + 8) * ASTRIDE + k + tig];
                af[t][2] = asu[m * ASTRIDE + k + tig + 4];
                af[t][3] = asu[(m + 8) * ASTRIDE + k + tig + 4];
            }
#pragma unroll
            for (int u = 0; u < 8; u++) {
                const int n = nbase + u * 8 + g;
                const uint32_t b0 = bsu[(k + tig) * BSTRIDE + n];
                const uint32_t b1 = bsu[(k + tig + 4) * BSTRIDE + n];
#pragma unroll
                for (int t = 0; t < 2; t++)
                    mma_tf32(acc[t][u][0], acc[t][u][1], acc[t][u][2], acc[t][u][3],
                             af[t][0], af[t][1], af[t][2], af[t][3], b0, b1);
            }
        }
        __syncthreads();
    }

    // epilogue: relu + store
    float* Cp = hout + (size_t)batch * NNODES * HID + (size_t)m0 * HID;
#pragma unroll
    for (int t = 0; t < 2; t++) {
        const int r0 = mbase + t * 16 + g;
#pragma unroll
        for (int u = 0; u < 8; u++) {
            const int c = nbase + u * 8 + 2 * tig;
            float2 v0 = { fmaxf(acc[t][u][0], 0.0f), fmaxf(acc[t][u][1], 0.0f) };
            float2 v1 = { fmaxf(acc[t][u][2], 0.0f), fmaxf(acc[t][u][3], 0.0f) };
            *(float2*)(Cp + (size_t)r0 * HID + c)       = v0;
            *(float2*)(Cp + (size_t)(r0 + 8) * HID + c) = v1;
        }
    }
}

// =========================================================================
// Linear layer (fp32 FFMA): C[M,128] = A[M,K] @ W[K,128] + b
// ROUND: RNA-round output to tf32 bits (for agg consumption).
// =========================================================================
template<bool RELU, bool BIAS, bool ROUND>
__global__ __launch_bounds__(256)
void gemm128(const float* __restrict__ A, const float* __restrict__ B,
             const float* __restrict__ bias, float* __restrict__ C,
             int K, size_t sA, size_t sB, size_t sC)
{
    const int batch = blockIdx.y;
    const int m0    = blockIdx.x * 128;

    const float* Ap = A + (size_t)batch * sA + (size_t)m0 * K;
    const float* Bp = B + (size_t)batch * sB;
    float*       Cp = C + (size_t)batch * sC + (size_t)m0 * 128;

    __shared__ float As[8][128];
    __shared__ float Bs[8][128];

    const int tid = threadIdx.x;
    const int tx  = tid & 15;
    const int ty  = tid >> 4;

    const int a_row = tid >> 1;
    const int a_k   = (tid & 1) * 4;
    const int b_row = tid >> 5;
    const int b_col = (tid & 31) * 4;

    float acc[8][8];
#pragma unroll
    for (int i = 0; i < 8; i++)
#pragma unroll
        for (int j = 0; j < 8; j++) acc[i][j] = 0.0f;

    const int ktiles = K >> 3;
    float4 ra = *(const float4*)(Ap + (size_t)a_row * K + a_k);
    float4 rb = *(const float4*)(Bp + (size_t)b_row * 128 + b_col);

    for (int kt = 0; kt < ktiles; kt++) {
        As[a_k + 0][a_row] = ra.x;
        As[a_k + 1][a_row] = ra.y;
        As[a_k + 2][a_row] = ra.z;
        As[a_k + 3][a_row] = ra.w;
        *(float4*)&Bs[b_row][b_col] = rb;
        __syncthreads();

        if (kt + 1 < ktiles) {
            const int kn = (kt + 1) * 8;
            ra = *(const float4*)(Ap + (size_t)a_row * K + kn + a_k);
            rb = *(const float4*)(Bp + (size_t)(kn + b_row) * 128 + b_col);
        }

#pragma unroll
        for (int kk = 0; kk < 8; kk++) {
            float af[8], bf[8];
            *(float4*)&af[0] = *(const float4*)&As[kk][ty * 4];
            *(float4*)&af[4] = *(const float4*)&As[kk][64 + ty * 4];
            *(float4*)&bf[0] = *(const float4*)&Bs[kk][tx * 4];
            *(float4*)&bf[4] = *(const float4*)&Bs[kk][64 + tx * 4];
#pragma unroll
            for (int i = 0; i < 8; i++)
#pragma unroll
                for (int j = 0; j < 8; j++)
                    acc[i][j] += af[i] * bf[j];
        }
        __syncthreads();
    }

    float bfrag[8];
    if (BIAS) {
#pragma unroll
        for (int q = 0; q < 4; q++) {
            bfrag[q]     = bias[tx * 4 + q];
            bfrag[4 + q] = bias[64 + tx * 4 + q];
        }
    }

#pragma unroll
    for (int i = 0; i < 8; i++) {
        const int row = (i < 4) ? (ty * 4 + i) : (64 + ty * 4 + (i - 4));
#pragma unroll
        for (int jg = 0; jg < 2; jg++) {
            float4 v;
            float* vp = &v.x;
#pragma unroll
            for (int q = 0; q < 4; q++) {
                float x = acc[i][jg * 4 + q];
                if (BIAS) x += bfrag[jg * 4 + q];
                if (RELU) x = fmaxf(x, 0.0f);
                if (ROUND) x = __uint_as_float(cvt_rna_tf32(x));
                vp[q] = x;
            }
            *(float4*)(Cp + (size_t)row * 128 + jg * 64 + tx * 4) = v;
        }
    }
}

// =========================================================================
// Output projection: out = (h @ Wout + bout) * mask
// =========================================================================
__global__ __launch_bounds__(256)
void final_proj_kernel(const float* __restrict__ h, const float* __restrict__ W,
                       const float* __restrict__ bias, const float* __restrict__ mask,
                       float* __restrict__ out)
{
    __shared__ float Ws[128][64];
    __shared__ float xs[16][128];
    __shared__ float bs[64];

    const int tid = threadIdx.x;
    for (int i = tid; i < 2048; i += 256)
        ((float4*)&Ws[0][0])[i] = ((const float4*)W)[i];
    if (tid < 64) bs[tid] = bias[tid];

    const int row0 = blockIdx.x * 16;
    for (int i = tid; i < 512; i += 256)
        ((float4*)&xs[0][0])[i] = *(const float4*)(h + (size_t)row0 * 128 + i * 4);
    __syncthreads();

    const int rl = tid >> 4;
    const int c4 = (tid & 15) * 4;

    float acc[4];
#pragma unroll
    for (int q = 0; q < 4; q++) acc[q] = bs[c4 + q];

#pragma unroll 8
    for (int d = 0; d < 128; d++) {
        const float x = xs[rl][d];
        const float4 w = *(const float4*)&Ws[d][c4];
        acc[0] += x * w.x;
        acc[1] += x * w.y;
        acc[2] += x * w.z;
        acc[3] += x * w.w;
    }

    const float m = mask[row0 + rl];
    float4 v = {acc[0] * m, acc[1] * m, acc[2] * m, acc[3] * m};
    *(float4*)(out + (size_t)(row0 + rl) * 64 + c4) = v;
}

// =========================================================================
// Launcher
// =========================================================================
extern "C" void kernel_launch(void* const* d_in, const int* in_sizes, int n_in,
                              void* d_out, int out_size)
{
    const float* latent = (const float*)d_in[0];
    const float* adj    = (const float*)d_in[1];
    const float* mask   = (const float*)d_in[2];
    const float* W0     = (const float*)d_in[3];
    const float* b0     = (const float*)d_in[4];
    const float* W1     = (const float*)d_in[5];
    const float* b1     = (const float*)d_in[6];
    const float* W2     = (const float*)d_in[7];
    const float* b2     = (const float*)d_in[8];
    const float* Wout   = (const float*)d_in[9];
    const float* bout   = (const float*)d_in[10];
    float*       out    = (float*)d_out;

    float *buf0 = nullptr, *buf1 = nullptr, *adj32 = nullptr;
    cudaGetSymbolAddress((void**)&buf0, g_buf0);
    cudaGetSymbolAddress((void**)&buf1, g_buf1);
    cudaGetSymbolAddress((void**)&adj32, g_adj32);

    cudaFuncSetAttribute(agg_mma_kernel,
                         cudaFuncAttributeMaxDynamicSharedMemorySize, AGG_SMEM);

    const dim3 gridLin(ROWS_T / 128, 1);
    const dim3 gridAgg(NNODES / 128, BATCH);   // 16 x 8 = 128 CTAs

    // pre-round adjacency to tf32 bits (used by all 3 agg GEMMs)
    round_adj_kernel<<<4096, 256>>>(adj, adj32);

    // layer 0
    gemm128<false, true, true><<<gridLin, 256>>>(latent, W0, b0, buf0, 64, 0, 0, 0);
    agg_mma_kernel<<<gridAgg, 256, AGG_SMEM>>>(adj32, buf0, buf1);

    // layer 1
    gemm128<false, true, true><<<gridLin, 256>>>(buf1, W1, b1, buf0, 128, 0, 0, 0);
    agg_mma_kernel<<<gridAgg, 256, AGG_SMEM>>>(adj32, buf0, buf1);

    // layer 2
    gemm128<false, true, true><<<gridLin, 256>>>(buf1, W2, b2, buf0, 128, 0, 0, 0);
    agg_mma_kernel<<<gridAgg, 256, AGG_SMEM>>>(adj32, buf0, buf1);

    // output projection + mask
    final_proj_kernel<<<ROWS_T / 16, 256>>>(buf1, Wout, bout, mask, out);
}

// round 7
// speedup vs baseline: 2.8489x; 1.1865x over previous
#include <cuda_runtime.h>
#include <cstdint>

// =========================================================================
// EuclideanGraphDecoder on GB300 (sm_103a via compute_103 baseline PTX)
// B=8, N=2048, latent=64, hidden=128, out=64, NORM=1.
//
// R7: ONE unified tf32 mma.sync GEMM kernel (cp.async 4-stage pipeline) for
// both the linear layers and the adjacency aggregation. RNA tf32 rounding of
// raw operands happens in registers at fragment-load time (no pre-round
// kernel, no rounded adjacency copy). Linear epilogue pre-rounds msg so the
// agg's B operand skips the cvt.
// =========================================================================

#define BATCH   8
#define NNODES  2048
#define HID     128
#define ROWS_T  (BATCH * NNODES)     // 16384

__device__ float g_buf0[ROWS_T * HID];     // msg (node-major, tf32-rounded)
__device__ float g_buf1[ROWS_T * HID];     // h   (node-major, fp32)

// ---------------------------------------------------------------- helpers
__device__ __forceinline__ uint32_t cvt_rna_tf32(float x) {
    uint32_t y;
    asm("cvt.rna.tf32.f32 %0, %1;" : "=r"(y) : "f"(x));
    return y;
}
__device__ __forceinline__ uint32_t cvt_rna_tf32_u(uint32_t x) {
    uint32_t y;
    asm("cvt.rna.tf32.f32 %0, %1;" : "=r"(y) : "r"(x));
    return y;
}
__device__ __forceinline__ uint32_t smem_u32(const void* p) {
    uint32_t a;
    asm("{ .reg .u64 t; cvta.to.shared.u64 t, %1; cvt.u32.u64 %0, t; }" : "=r"(a) : "l"(p));
    return a;
}
__device__ __forceinline__ void cp_async16(uint32_t dst, const void* src) {
    asm volatile("cp.async.cg.shared.global [%0], [%1], 16;" :: "r"(dst), "l"(src));
}
#define CP_COMMIT() asm volatile("cp.async.commit_group;" ::: "memory")

__device__ __forceinline__ void mma_tf32(float& c0, float& c1, float& c2, float& c3,
                                         uint32_t a0, uint32_t a1, uint32_t a2, uint32_t a3,
                                         uint32_t b0, uint32_t b1) {
    asm volatile(
        "mma.sync.aligned.m16n8k8.row.col.f32.tf32.tf32.f32 "
        "{%0,%1,%2,%3}, {%4,%5,%6,%7}, {%8,%9}, {%0,%1,%2,%3};"
        : "+f"(c0), "+f"(c1), "+f"(c2), "+f"(c3)
        : "r"(a0), "r"(a1), "r"(a2), "r"(a3), "r"(b0), "r"(b1));
}

// =========================================================================
// Unified tf32 GEMM:  C[b, m0:m0+128, 0:128] = op( A[b, rows, 0:K] @ B[b, 0:K, 0:128] )
//   A row-major (lda runtime), B row-major (ldb = 128 always).
//   CTA 128x128, K in BK=32 chunks, 4-stage cp.async pipeline.
//   8 warps 4(M)x2(N); warp tile 32x64 = 2x8 m16n8k8.
//   A fragments are always RNA-rounded in registers (raw fp32 input).
//   CVTB: round B fragments too (raw weights); else B is pre-rounded.
//   Epilogue: +bias (BIAS), relu (RELU), RNA-round output (ROUND).
// =========================================================================
#define BK      32
#define STG     4
#define ASTRIDE 36
#define BSTRIDE 136
#define A_FLTS  (128 * ASTRIDE)      // 4608
#define B_FLTS  (BK * BSTRIDE)       // 4352
#define STG_FLTS (A_FLTS + B_FLTS)   // 8960
#define GEMM_SMEM (STG * STG_FLTS * 4)   // 143360 bytes

__device__ __forceinline__ void stage_chunk(uint32_t smb, int s,
                                            const float* Ap, const float* Bp,
                                            int k0, int tid, int lda)
{
    const uint32_t sa = smb + (uint32_t)(s * STG_FLTS) * 4u;
    const uint32_t sb = sa + A_FLTS * 4u;
#pragma unroll
    for (int r = 0; r < 4; r++) {
        const int idx  = tid + 256 * r;
        const int arow = idx >> 3, aseg = idx & 7;
        cp_async16(sa + (uint32_t)(arow * ASTRIDE + aseg * 4) * 4u,
                   Ap + (size_t)arow * lda + k0 + aseg * 4);
        const int brow = idx >> 5, bseg = idx & 31;
        cp_async16(sb + (uint32_t)(brow * BSTRIDE + bseg * 4) * 4u,
                   Bp + (size_t)(k0 + brow) * HID + bseg * 4);
    }
    CP_COMMIT();
}

template<bool RELU, bool BIAS, bool ROUND, bool CVTB>
__global__ __launch_bounds__(256, 1)
void mma_gemm_kernel(const float* __restrict__ A, const float* __restrict__ B,
                     const float* __restrict__ bias, float* __restrict__ C,
                     int K, int lda, size_t sA, size_t sB, size_t sC)
{
    extern __shared__ float smf[];
    const uint32_t smb = smem_u32(smf);

    const int tid   = threadIdx.x;
    const int lane  = tid & 31;
    const int wid   = tid >> 5;
    const int g     = lane >> 2;       // 0..7
    const int tig   = lane & 3;        // 0..3
    const int mbase = (wid & 3) * 32;  // 4 warps along M
    const int nbase = (wid >> 2) * 64; // 2 warps along N

    const int batch = blockIdx.y;
    const int m0    = blockIdx.x * 128;

    const float* Ap = A + (size_t)batch * sA + (size_t)m0 * lda;
    const float* Bp = B + (size_t)batch * sB;

    float acc[2][8][4];
#pragma unroll
    for (int t = 0; t < 2; t++)
#pragma unroll
        for (int u = 0; u < 8; u++)
#pragma unroll
            for (int q = 0; q < 4; q++) acc[t][u][q] = 0.0f;

    const int kiters = K / BK;

    int committed = 0;
#pragma unroll
    for (int p = 0; p < STG - 1; p++)
        if (p < kiters) { stage_chunk(smb, p, Ap, Bp, p * BK, tid, lda); committed++; }

    for (int it = 0; it < kiters; it++) {
        const int pend = committed - it - 1;
        if (pend <= 0)      asm volatile("cp.async.wait_group 0;" ::: "memory");
        else if (pend == 1) asm volatile("cp.async.wait_group 1;" ::: "memory");
        else                asm volatile("cp.async.wait_group 2;" ::: "memory");
        __syncthreads();

        // refill the stage freed by the previous iteration
        if (it + STG - 1 < kiters) {
            stage_chunk(smb, (it + STG - 1) & (STG - 1), Ap, Bp, (it + STG - 1) * BK, tid, lda);
            committed++;
        }

        const uint32_t* asu = (const uint32_t*)(smf + (it & (STG - 1)) * STG_FLTS);
        const uint32_t* bsu = asu + A_FLTS;

#pragma unroll
        for (int ks = 0; ks < 4; ks++) {
            const int k = ks * 8;
            uint32_t af[2][4];
#pragma unroll
            for (int t = 0; t < 2; t++) {
                const int m = mbase + t * 16 + g;
                af[t][0] = cvt_rna_tf32_u(asu[m * ASTRIDE + k + tig]);
                af[t][1] = cvt_rna_tf32_u(asu[(m + 8) * ASTRIDE + k + tig]);
                af[t][2] = cvt_rna_tf32_u(asu[m * ASTRIDE + k + tig + 4]);
                af[t][3] = cvt_rna_tf32_u(asu[(m + 8) * ASTRIDE + k + tig + 4]);
            }
#pragma unroll
            for (int u = 0; u < 8; u++) {
                const int n = nbase + u * 8 + g;
                uint32_t b0 = bsu[(k + tig) * BSTRIDE + n];
                uint32_t b1 = bsu[(k + tig + 4) * BSTRIDE + n];
                if (CVTB) { b0 = cvt_rna_tf32_u(b0); b1 = cvt_rna_tf32_u(b1); }
#pragma unroll
                for (int t = 0; t < 2; t++)
                    mma_tf32(acc[t][u][0], acc[t][u][1], acc[t][u][2], acc[t][u][3],
                             af[t][0], af[t][1], af[t][2], af[t][3], b0, b1);
            }
        }
        __syncthreads();
    }

    // ---- epilogue ----
    float* Cp = C + (size_t)batch * sC + (size_t)m0 * HID;
#pragma unroll
    for (int t = 0; t < 2; t++) {
        const int r0 = mbase + t * 16 + g;
#pragma unroll
        for (int u = 0; u < 8; u++) {
            const int c = nbase + u * 8 + 2 * tig;
            float v[4] = { acc[t][u][0], acc[t][u][1], acc[t][u][2], acc[t][u][3] };
            if (BIAS) {
                const float bc0 = bias[c], bc1 = bias[c + 1];
                v[0] += bc0; v[1] += bc1; v[2] += bc0; v[3] += bc1;
            }
#pragma unroll
            for (int q = 0; q < 4; q++) {
                if (RELU)  v[q] = fmaxf(v[q], 0.0f);
                if (ROUND) v[q] = __uint_as_float(cvt_rna_tf32(v[q]));
            }
            float2 v0 = { v[0], v[1] };
            float2 v1 = { v[2], v[3] };
            *(float2*)(Cp + (size_t)r0 * HID + c)       = v0;
            *(float2*)(Cp + (size_t)(r0 + 8) * HID + c) = v1;
        }
    }
}

// =========================================================================
// Output projection: out = (h @ Wout + bout) * mask     (fp32 FFMA)
// =========================================================================
__global__ __launch_bounds__(256)
void final_proj_kernel(const float* __restrict__ h, const float* __restrict__ W,
                       const float* __restrict__ bias, const float* __restrict__ mask,
                       float* __restrict__ out)
{
    __shared__ float Ws[128][64];
    __shared__ float xs[16][128];
    __shared__ float bs[64];

    const int tid = threadIdx.x;
    for (int i = tid; i < 2048; i += 256)
        ((float4*)&Ws[0][0])[i] = ((const float4*)W)[i];
    if (tid < 64) bs[tid] = bias[tid];

    const int row0 = blockIdx.x * 16;
    for (int i = tid; i < 512; i += 256)
        ((float4*)&xs[0][0])[i] = *(const float4*)(h + (size_t)row0 * 128 + i * 4);
    __syncthreads();

    const int rl = tid >> 4;
    const int c4 = (tid & 15) * 4;

    float acc[4];
#pragma unroll
    for (int q = 0; q < 4; q++) acc[q] = bs[c4 + q];

#pragma unroll 8
    for (int d = 0; d < 128; d++) {
        const float x = xs[rl][d];
        const float4 w = *(const float4*)&Ws[d][c4];
        acc[0] += x * w.x;
        acc[1] += x * w.y;
        acc[2] += x * w.z;
        acc[3] += x * w.w;
    }

    const float m = mask[row0 + rl];
    float4 v = {acc[0] * m, acc[1] * m, acc[2] * m, acc[3] * m};
    *(float4*)(out + (size_t)(row0 + rl) * 64 + c4) = v;
}

// =========================================================================
// Launcher
// =========================================================================
extern "C" void kernel_launch(void* const* d_in, const int* in_sizes, int n_in,
                              void* d_out, int out_size)
{
    const float* latent = (const float*)d_in[0];
    const float* adj    = (const float*)d_in[1];
    const float* mask   = (const float*)d_in[2];
    const float* W0     = (const float*)d_in[3];
    const float* b0     = (const float*)d_in[4];
    const float* W1     = (const float*)d_in[5];
    const float* b1     = (const float*)d_in[6];
    const float* W2     = (const float*)d_in[7];
    const float* b2     = (const float*)d_in[8];
    const float* Wout   = (const float*)d_in[9];
    const float* bout   = (const float*)d_in[10];
    float*       out    = (float*)d_out;

    float *buf0 = nullptr, *buf1 = nullptr;
    cudaGetSymbolAddress((void**)&buf0, g_buf0);
    cudaGetSymbolAddress((void**)&buf1, g_buf1);

    // linear: bias + round-output, B (weights) cvt'd in regs
    auto lin = mma_gemm_kernel<false, true, true, true>;
    // agg: relu only, B (msg) pre-rounded
    auto agg = mma_gemm_kernel<true, false, false, false>;
    cudaFuncSetAttribute(lin, cudaFuncAttributeMaxDynamicSharedMemorySize, GEMM_SMEM);
    cudaFuncSetAttribute(agg, cudaFuncAttributeMaxDynamicSharedMemorySize, GEMM_SMEM);

    const dim3 gridLin(ROWS_T / 128, 1);       // 128 CTAs, batch folded into M
    const dim3 gridAgg(NNODES / 128, BATCH);   // 16 x 8 = 128 CTAs
    const size_t sAdj = (size_t)NNODES * NNODES;
    const size_t sH   = (size_t)NNODES * HID;

    // layer 0:  msg = latent @ W0 + b0  (K=64), then h = relu(adj @ msg)
    lin<<<gridLin, 256, GEMM_SMEM>>>(latent, W0, b0, buf0, 64, 64, 0, 0, 0);
    agg<<<gridAgg, 256, GEMM_SMEM>>>(adj, buf0, nullptr, buf1, NNODES, NNODES, sAdj, sH, sH);

    // layer 1
    lin<<<gridLin, 256, GEMM_SMEM>>>(buf1, W1, b1, buf0, 128, 128, 0, 0, 0);
    agg<<<gridAgg, 256, GEMM_SMEM>>>(adj, buf0, nullptr, buf1, NNODES, NNODES, sAdj, sH, sH);

    // layer 2
    lin<<<gridLin, 256, GEMM_SMEM>>>(buf1, W2, b2, buf0, 128, 128, 0, 0, 0);
    agg<<<gridAgg, 256, GEMM_SMEM>>>(adj, buf0, nullptr, buf1, NNODES, NNODES, sAdj, sH, sH);

    // output projection + mask
    final_proj_kernel<<<ROWS_T / 16, 256>>>(buf1, Wout, bout, mask, out);
}